// round 1
// baseline (speedup 1.0000x reference)
#include <cuda_runtime.h>
#include <cuda_bf16.h>
#include <cstdint>

// adj is (N+4)x(N+4), N=8192 (derived from in_sizes[0] = N*C with C=2048,
// but we compute N from the output size to be shape-robust):
//   adj[i][i]  = 1.0   for i <  N
//   adj[i][j]  = 0.25  for i >= N and j >= N   (4x4 block)
//   adj[i][j]  = 0.0   otherwise
//
// Pure write-only fill, HBM-store-bound. float4 stores, 2D grid (no int div).

__global__ void adj_fill_kernel(float4* __restrict__ out, int M, int N) {
    const int row  = blockIdx.y;                                   // 0..M-1
    const int q    = blockIdx.x * blockDim.x + threadIdx.x;        // float4 index in row
    const int col0 = q << 2;                                       // first column of this float4
    if (col0 >= M) return;

    float4 v = make_float4(0.f, 0.f, 0.f, 0.f);

    if (row < N) {
        // possible diagonal hit
        const int d = row - col0;            // which lane holds the diagonal, if any
        if (d == 0) v.x = 1.0f;
        else if (d == 1) v.y = 1.0f;
        else if (d == 2) v.z = 1.0f;
        else if (d == 3) v.w = 1.0f;
    } else {
        // bottom 4 rows: columns >= N get 0.25
        if (col0 + 0 >= N) v.x = 0.25f;
        if (col0 + 1 >= N) v.y = 0.25f;
        if (col0 + 2 >= N) v.z = 0.25f;
        if (col0 + 3 >= N) v.w = 0.25f;
    }

    // Row length M is divisible by 4, so rows stay float4-aligned.
    out[(size_t)row * (size_t)(M >> 2) + (size_t)q] = v;
}

extern "C" void kernel_launch(void* const* d_in, const int* in_sizes, int n_in,
                              void* d_out, int out_size) {
    (void)d_in; (void)in_sizes; (void)n_in;

    // out_size = M*M. Recover M (M = N+4, N = 8192 expected -> M = 8196).
    // integer sqrt via float then fixup
    int M = (int)(sqrtf((float)(double)out_size));
    while ((long long)M * M > (long long)out_size) --M;
    while ((long long)(M + 1) * (M + 1) <= (long long)out_size) ++M;
    const int N = M - 4;

    const int q_per_row = M >> 2;                 // float4s per row (M divisible by 4)
    const int threads = 256;
    dim3 grid((q_per_row + threads - 1) / threads, M, 1);
    adj_fill_kernel<<<grid, threads>>>((float4*)d_out, M, N);
}

// round 2
// speedup vs baseline: 1.0415x; 1.0415x over previous
#include <cuda_runtime.h>
#include <cuda_bf16.h>
#include <cstdint>

// adj is (N+4)x(N+4), N=8192:
//   adj[i][i]  = 1.0   for i <  N
//   adj[i][j]  = 0.25  for i >= N and j >= N   (4x4 block)
//   adj[i][j]  = 0.0   otherwise
//
// Pure write-only HBM-bound fill. One block per row; each thread issues ~8
// independent STG.128 (streaming .cs hint) per row to amortize index math.

__global__ __launch_bounds__(256) void adj_fill_kernel(float4* __restrict__ out,
                                                       int M, int N) {
    const int row = blockIdx.x;          // 0..M-1
    const int qpr = M >> 2;              // float4s per row (M divisible by 4)
    float4* __restrict__ rowp = out + (size_t)row * (size_t)qpr;

    const float4 z = make_float4(0.f, 0.f, 0.f, 0.f);

    if (row < N) {
        // Exactly one float4 in this row holds the diagonal 1.0.
        const int rq = row >> 2;         // float4 index containing the diagonal
        const int rl = row & 3;          // lane within that float4
        #pragma unroll 4
        for (int q = threadIdx.x; q < qpr; q += 256) {
            float4 v = z;
            if (q == rq) {
                // set lane rl to 1.0
                float* f = reinterpret_cast<float*>(&v);
                f[rl] = 1.0f;
            }
            __stcs(rowp + q, v);
        }
    } else {
        // Bottom 4 rows: columns >= N are 0.25, else 0.
        #pragma unroll 4
        for (int q = threadIdx.x; q < qpr; q += 256) {
            const int c = q << 2;
            float4 v;
            v.x = (c + 0 >= N) ? 0.25f : 0.f;
            v.y = (c + 1 >= N) ? 0.25f : 0.f;
            v.z = (c + 2 >= N) ? 0.25f : 0.f;
            v.w = (c + 3 >= N) ? 0.25f : 0.f;
            __stcs(rowp + q, v);
        }
    }
}

extern "C" void kernel_launch(void* const* d_in, const int* in_sizes, int n_in,
                              void* d_out, int out_size) {
    (void)d_in; (void)in_sizes; (void)n_in;

    // out_size = M*M. Recover M (expected 8196).
    int M = (int)(sqrtf((float)(double)out_size));
    while ((long long)M * M > (long long)out_size) --M;
    while ((long long)(M + 1) * (M + 1) <= (long long)out_size) ++M;
    const int N = M - 4;

    adj_fill_kernel<<<M, 256>>>((float4*)d_out, M, N);
}